// round 9
// baseline (speedup 1.0000x reference)
#include <cuda_runtime.h>

// Conv2D 7x7, stride 1, pad 3. X [64,1024,1024] fp32 -> out [64,1024,1024].
// R8: identical compute to R7 (ir-outer single-load-per-row + FFMA2 phase
// trick + constant-bank weights + cp.async double-buffer), occupancy raised
// to 4 blocks/SM to hide sync/load/epilogue time under other blocks' FFMA2.

#define IMG 1024
#define KS 7
#define PAD 3

#define BX 32
#define BY 8
#define TX 4
#define TY 4
#define TILE_W (BX * TX)           // 128
#define CHUNK_H (BY * TY)          // 32 output rows per chunk
#define YGROUPS 2
#define YSPAN (IMG / YGROUPS)      // 512
#define NCHUNK (YSPAN / CHUNK_H)   // 16

#define IN_H (CHUNK_H + KS - 1)    // 38 input rows per chunk
#define PITCH 136                  // floats per smem row (544B, 16B-aligned)

typedef unsigned long long ull;

// Phase-pair weight tables.
// phase0: {w0,w1},{w2,w3},{w4,w5},{w6,0}
// phase1: {0,w0},{w1,w2},{w3,w4},{w5,w6}
__constant__ float2 cWp[KS][2][4];
__device__ float2 g_wp[KS][2][4];

__global__ void prep_weights(const float* __restrict__ W) {
    int t = threadIdx.x;
    if (t < KS * 8) {
        int ky = t >> 3;
        int r  = t & 7;
        int ph = r >> 2;
        int j  = r & 3;
        float lo, hi;
        if (ph == 0) {
            lo = W[ky * KS + 2 * j];
            hi = (2 * j + 1 < KS) ? W[ky * KS + 2 * j + 1] : 0.0f;
        } else {
            lo = (2 * j - 1 >= 0) ? W[ky * KS + 2 * j - 1] : 0.0f;
            hi = W[ky * KS + 2 * j];
        }
        g_wp[ky][ph][j] = make_float2(lo, hi);
    }
}

__device__ __forceinline__ void ffma2(ull& d, ull a, ull b) {
    asm("fma.rn.f32x2 %0, %1, %2, %0;" : "+l"(d) : "l"(a), "l"(b));
}
__device__ __forceinline__ ull pack2c(float2 v) {
    ull r;
    asm("mov.b64 %0, {%1, %2};" : "=l"(r) : "f"(v.x), "f"(v.y));
    return r;
}
__device__ __forceinline__ void unpack2(ull v, float& lo, float& hi) {
    asm("mov.b64 {%0, %1}, %2;" : "=f"(lo), "=f"(hi) : "l"(v));
}
template <int N>
__device__ __forceinline__ void cp_wait_group() {
    asm volatile("cp.async.wait_group %0;" :: "n"(N));
}
__device__ __forceinline__ void cp16(float* dst_smem, const float* src, bool ok) {
    unsigned saddr = (unsigned)__cvta_generic_to_shared(dst_smem);
    unsigned ss = ok ? 16u : 0u;
    asm volatile("cp.async.cg.shared.global [%0], [%1], 16, %2;"
                 :: "r"(saddr), "l"(src), "r"(ss));
}

__global__ __launch_bounds__(BX * BY, 4)
void conv7x7_kernel(const float* __restrict__ X,
                    float* __restrict__ out) {
    __shared__ __align__(16) float s_buf[2][IN_H * PITCH];

    const int tid = threadIdx.y * BX + threadIdx.x;

    const int tileX0 = blockIdx.x * TILE_W;
    const int yBase  = blockIdx.y * YSPAN;
    const int b      = blockIdx.z;
    const float* Xb  = X + (size_t)b * IMG * IMG;
    float* outb      = out + (size_t)b * IMG * IMG;

    const int gx0 = tileX0 - 4;           // 16B-aligned halo start

    // Per-thread cp.async addressing (hoisted; no division)
    const int c4m  = tid & 31;            // main col4 0..31
    const int r0m  = tid >> 5;            // row 0..7 (+8k)
    const int gxm  = gx0 + c4m * 4;
    const bool okxm = (gxm >= 0) && (gxm < IMG);
    const int rt_  = tid >> 1;            // tail row (tid < 76)
    const int c4t  = 32 + (tid & 1);
    const int gxt  = gx0 + c4t * 4;
    const bool okxt = (gxt < IMG);
    const bool tailact = (tid < 2 * IN_H);

    const int lx  = threadIdx.x * TX;     // local output col (multiple of 4)
    const int ly  = threadIdx.y * TY;     // local output row

#define ISSUE_CHUNK(SBUF, GY0)                                                  \
    do {                                                                        \
        const int gy0_ = (GY0);                                                 \
        _Pragma("unroll")                                                       \
        for (int k = 0; k < 5; ++k) {                                           \
            int r_ = r0m + k * 8;                                               \
            if (k < 4 || r_ < IN_H) {                                           \
                int gy_ = gy0_ + r_;                                            \
                bool ok_ = okxm && (gy_ >= 0) && (gy_ < IMG);                   \
                const float* src_ = ok_ ? (Xb + (size_t)gy_ * IMG + gxm) : Xb;  \
                cp16(&(SBUF)[r_ * PITCH + c4m * 4], src_, ok_);                 \
            }                                                                   \
        }                                                                       \
        if (tailact) {                                                          \
            int gy_ = gy0_ + rt_;                                               \
            bool ok_ = okxt && (gy_ >= 0) && (gy_ < IMG);                       \
            const float* src_ = ok_ ? (Xb + (size_t)gy_ * IMG + gxt) : Xb;      \
            cp16(&(SBUF)[rt_ * PITCH + c4t * 4], src_, ok_);                    \
        }                                                                       \
        asm volatile("cp.async.commit_group;");                                 \
    } while (0)

    // Prologue: load chunk 0
    ISSUE_CHUNK(s_buf[0], yBase - PAD);

    for (int c = 0; c < NCHUNK; ++c) {
        if (c + 1 < NCHUNK)
            ISSUE_CHUNK(s_buf[(c + 1) & 1], yBase + (c + 1) * CHUNK_H - PAD);

        if (c + 1 < NCHUNK) cp_wait_group<1>();
        else                cp_wait_group<0>();
        __syncthreads();

        const float* buf = s_buf[c & 1];

        ull acc[TY][TX];
#pragma unroll
        for (int ry = 0; ry < TY; ++ry)
#pragma unroll
            for (int ox = 0; ox < TX; ++ox) acc[ry][ox] = 0ull;

        // ir-outer: each input row loaded ONCE; feeds all valid
        // (ry, ky = ir - ry) cells. All guards are compile-time.
#pragma unroll
        for (int ir = 0; ir < TY + KS - 1; ++ir) {
            const ulonglong2* rowp = reinterpret_cast<const ulonglong2*>(
                &buf[(ly + ir) * PITCH + lx]);
            ulonglong2 q0 = rowp[0];   // p0, p1
            ulonglong2 q1 = rowp[1];   // p2, p3
            ulonglong2 q2 = rowp[2];   // p4, p5

#pragma unroll
            for (int ry = 0; ry < TY; ++ry) {
                const int ky = ir - ry;
                if (ky >= 0 && ky < KS) {
                    // 8 weight pairs for this ky from the constant bank
                    ull wa0 = pack2c(cWp[ky][0][0]);
                    ull wa1 = pack2c(cWp[ky][0][1]);
                    ull wb0 = pack2c(cWp[ky][0][2]);
                    ull wb1 = pack2c(cWp[ky][0][3]);
                    ull wc0 = pack2c(cWp[ky][1][0]);
                    ull wc1 = pack2c(cWp[ky][1][1]);
                    ull wd0 = pack2c(cWp[ky][1][2]);
                    ull wd1 = pack2c(cWp[ky][1][3]);

                    // ox=0: phase1 over p0..p3
                    ffma2(acc[ry][0], q0.x, wc0); ffma2(acc[ry][0], q0.y, wc1);
                    ffma2(acc[ry][0], q1.x, wd0); ffma2(acc[ry][0], q1.y, wd1);
                    // ox=1: phase0 over p1..p4
                    ffma2(acc[ry][1], q0.y, wa0); ffma2(acc[ry][1], q1.x, wa1);
                    ffma2(acc[ry][1], q1.y, wb0); ffma2(acc[ry][1], q2.x, wb1);
                    // ox=2: phase1 over p1..p4
                    ffma2(acc[ry][2], q0.y, wc0); ffma2(acc[ry][2], q1.x, wc1);
                    ffma2(acc[ry][2], q1.y, wd0); ffma2(acc[ry][2], q2.x, wd1);
                    // ox=3: phase0 over p2..p5
                    ffma2(acc[ry][3], q1.x, wa0); ffma2(acc[ry][3], q1.y, wa1);
                    ffma2(acc[ry][3], q2.x, wb0); ffma2(acc[ry][3], q2.y, wb1);
                }
            }
        }

        // Store chunk results (aligned float4)
        const int ox0 = tileX0 + lx;
        const int oy0 = yBase + c * CHUNK_H + ly;
#pragma unroll
        for (int ry = 0; ry < TY; ++ry) {
            float4 v;
            float lo, hi;
            unpack2(acc[ry][0], lo, hi); v.x = lo + hi;
            unpack2(acc[ry][1], lo, hi); v.y = lo + hi;
            unpack2(acc[ry][2], lo, hi); v.z = lo + hi;
            unpack2(acc[ry][3], lo, hi); v.w = lo + hi;
            *reinterpret_cast<float4*>(&outb[(size_t)(oy0 + ry) * IMG + ox0]) = v;
        }

        __syncthreads();
    }
#undef ISSUE_CHUNK
}

extern "C" void kernel_launch(void* const* d_in, const int* in_sizes, int n_in,
                              void* d_out, int out_size) {
    const float* X = (const float*)d_in[0];
    const float* W = (const float*)d_in[1];
    float* out = (float*)d_out;

    // Build phase-pair table in device scratch, then stage into the constant
    // bank (device-to-device, graph-capturable).
    prep_weights<<<1, 64>>>(W);
    void* dst = nullptr;
    void* src = nullptr;
    cudaGetSymbolAddress(&dst, cWp);
    cudaGetSymbolAddress(&src, g_wp);
    cudaMemcpyAsync(dst, src, sizeof(g_wp), cudaMemcpyDeviceToDevice);

    dim3 block(BX, BY);
    dim3 grid(IMG / TILE_W, YGROUPS, 64);
    conv7x7_kernel<<<grid, block>>>(X, out);
}

// round 10
// speedup vs baseline: 1.0030x; 1.0030x over previous
#include <cuda_runtime.h>

// Conv2D 7x7, stride 1, pad 3. X [64,1024,1024] fp32 -> out [64,1024,1024].
// R10: same validated compute as R7/R9 (ir-outer single-load-per-row + FFMA2
// phase trick + constant-bank weights + cp.async double-buffer), but the tile
// buffer is DYNAMIC smem with an explicit max-shared carveout so 4 blocks/SM
// actually become resident (R9 showed launch_bounds alone cannot do it).

#define IMG 1024
#define KS 7
#define PAD 3

#define BX 32
#define BY 8
#define TX 4
#define TY 4
#define TILE_W (BX * TX)           // 128
#define CHUNK_H (BY * TY)          // 32 output rows per chunk
#define YGROUPS 2
#define YSPAN (IMG / YGROUPS)      // 512
#define NCHUNK (YSPAN / CHUNK_H)   // 16

#define IN_H (CHUNK_H + KS - 1)    // 38 input rows per chunk
#define PITCH 136                  // floats per smem row (544B, 16B-aligned)
#define SMEM_BYTES (2 * IN_H * PITCH * 4)   // 41344

typedef unsigned long long ull;

// Phase-pair weight tables.
// phase0: {w0,w1},{w2,w3},{w4,w5},{w6,0}
// phase1: {0,w0},{w1,w2},{w3,w4},{w5,w6}
__constant__ float2 cWp[KS][2][4];
__device__ float2 g_wp[KS][2][4];

__global__ void prep_weights(const float* __restrict__ W) {
    int t = threadIdx.x;
    if (t < KS * 8) {
        int ky = t >> 3;
        int r  = t & 7;
        int ph = r >> 2;
        int j  = r & 3;
        float lo, hi;
        if (ph == 0) {
            lo = W[ky * KS + 2 * j];
            hi = (2 * j + 1 < KS) ? W[ky * KS + 2 * j + 1] : 0.0f;
        } else {
            lo = (2 * j - 1 >= 0) ? W[ky * KS + 2 * j - 1] : 0.0f;
            hi = W[ky * KS + 2 * j];
        }
        g_wp[ky][ph][j] = make_float2(lo, hi);
    }
}

__device__ __forceinline__ void ffma2(ull& d, ull a, ull b) {
    asm("fma.rn.f32x2 %0, %1, %2, %0;" : "+l"(d) : "l"(a), "l"(b));
}
__device__ __forceinline__ ull pack2c(float2 v) {
    ull r;
    asm("mov.b64 %0, {%1, %2};" : "=l"(r) : "f"(v.x), "f"(v.y));
    return r;
}
__device__ __forceinline__ void unpack2(ull v, float& lo, float& hi) {
    asm("mov.b64 {%0, %1}, %2;" : "=f"(lo), "=f"(hi) : "l"(v));
}
template <int N>
__device__ __forceinline__ void cp_wait_group() {
    asm volatile("cp.async.wait_group %0;" :: "n"(N));
}
__device__ __forceinline__ void cp16(float* dst_smem, const float* src, bool ok) {
    unsigned saddr = (unsigned)__cvta_generic_to_shared(dst_smem);
    unsigned ss = ok ? 16u : 0u;
    asm volatile("cp.async.cg.shared.global [%0], [%1], 16, %2;"
                 :: "r"(saddr), "l"(src), "r"(ss));
}

__global__ __launch_bounds__(BX * BY, 4)
void conv7x7_kernel(const float* __restrict__ X,
                    float* __restrict__ out) {
    extern __shared__ __align__(16) float s_dyn[];
    float* s_buf0 = s_dyn;                       // [IN_H * PITCH]
    float* s_buf1 = s_dyn + IN_H * PITCH;        // [IN_H * PITCH]

    const int tid = threadIdx.y * BX + threadIdx.x;

    const int tileX0 = blockIdx.x * TILE_W;
    const int yBase  = blockIdx.y * YSPAN;
    const int b      = blockIdx.z;
    const float* Xb  = X + (size_t)b * IMG * IMG;
    float* outb      = out + (size_t)b * IMG * IMG;

    const int gx0 = tileX0 - 4;           // 16B-aligned halo start

    // Per-thread cp.async addressing (hoisted; no division)
    const int c4m  = tid & 31;            // main col4 0..31
    const int r0m  = tid >> 5;            // row 0..7 (+8k)
    const int gxm  = gx0 + c4m * 4;
    const bool okxm = (gxm >= 0) && (gxm < IMG);
    const int rt_  = tid >> 1;            // tail row (tid < 76)
    const int c4t  = 32 + (tid & 1);
    const int gxt  = gx0 + c4t * 4;
    const bool okxt = (gxt < IMG);
    const bool tailact = (tid < 2 * IN_H);

    const int lx  = threadIdx.x * TX;     // local output col (multiple of 4)
    const int ly  = threadIdx.y * TY;     // local output row

#define ISSUE_CHUNK(SBUF, GY0)                                                  \
    do {                                                                        \
        const int gy0_ = (GY0);                                                 \
        _Pragma("unroll")                                                       \
        for (int k = 0; k < 5; ++k) {                                           \
            int r_ = r0m + k * 8;                                               \
            if (k < 4 || r_ < IN_H) {                                           \
                int gy_ = gy0_ + r_;                                            \
                bool ok_ = okxm && (gy_ >= 0) && (gy_ < IMG);                   \
                const float* src_ = ok_ ? (Xb + (size_t)gy_ * IMG + gxm) : Xb;  \
                cp16(&(SBUF)[r_ * PITCH + c4m * 4], src_, ok_);                 \
            }                                                                   \
        }                                                                       \
        if (tailact) {                                                          \
            int gy_ = gy0_ + rt_;                                               \
            bool ok_ = okxt && (gy_ >= 0) && (gy_ < IMG);                       \
            const float* src_ = ok_ ? (Xb + (size_t)gy_ * IMG + gxt) : Xb;      \
            cp16(&(SBUF)[rt_ * PITCH + c4t * 4], src_, ok_);                    \
        }                                                                       \
        asm volatile("cp.async.commit_group;");                                 \
    } while (0)

    // Prologue: load chunk 0
    ISSUE_CHUNK(s_buf0, yBase - PAD);

    for (int c = 0; c < NCHUNK; ++c) {
        if (c + 1 < NCHUNK)
            ISSUE_CHUNK(((c + 1) & 1) ? s_buf1 : s_buf0,
                        yBase + (c + 1) * CHUNK_H - PAD);

        if (c + 1 < NCHUNK) cp_wait_group<1>();
        else                cp_wait_group<0>();
        __syncthreads();

        const float* buf = (c & 1) ? s_buf1 : s_buf0;

        ull acc[TY][TX];
#pragma unroll
        for (int ry = 0; ry < TY; ++ry)
#pragma unroll
            for (int ox = 0; ox < TX; ++ox) acc[ry][ox] = 0ull;

        // ir-outer: each input row loaded ONCE; feeds all valid
        // (ry, ky = ir - ry) cells. All guards are compile-time.
#pragma unroll
        for (int ir = 0; ir < TY + KS - 1; ++ir) {
            const ulonglong2* rowp = reinterpret_cast<const ulonglong2*>(
                &buf[(ly + ir) * PITCH + lx]);
            ulonglong2 q0 = rowp[0];   // p0, p1
            ulonglong2 q1 = rowp[1];   // p2, p3
            ulonglong2 q2 = rowp[2];   // p4, p5

#pragma unroll
            for (int ry = 0; ry < TY; ++ry) {
                const int ky = ir - ry;
                if (ky >= 0 && ky < KS) {
                    // 8 weight pairs for this ky from the constant bank
                    ull wa0 = pack2c(cWp[ky][0][0]);
                    ull wa1 = pack2c(cWp[ky][0][1]);
                    ull wb0 = pack2c(cWp[ky][0][2]);
                    ull wb1 = pack2c(cWp[ky][0][3]);
                    ull wc0 = pack2c(cWp[ky][1][0]);
                    ull wc1 = pack2c(cWp[ky][1][1]);
                    ull wd0 = pack2c(cWp[ky][1][2]);
                    ull wd1 = pack2c(cWp[ky][1][3]);

                    // ox=0: phase1 over p0..p3
                    ffma2(acc[ry][0], q0.x, wc0); ffma2(acc[ry][0], q0.y, wc1);
                    ffma2(acc[ry][0], q1.x, wd0); ffma2(acc[ry][0], q1.y, wd1);
                    // ox=1: phase0 over p1..p4
                    ffma2(acc[ry][1], q0.y, wa0); ffma2(acc[ry][1], q1.x, wa1);
                    ffma2(acc[ry][1], q1.y, wb0); ffma2(acc[ry][1], q2.x, wb1);
                    // ox=2: phase1 over p1..p4
                    ffma2(acc[ry][2], q0.y, wc0); ffma2(acc[ry][2], q1.x, wc1);
                    ffma2(acc[ry][2], q1.y, wd0); ffma2(acc[ry][2], q2.x, wd1);
                    // ox=3: phase0 over p2..p5
                    ffma2(acc[ry][3], q1.x, wa0); ffma2(acc[ry][3], q1.y, wa1);
                    ffma2(acc[ry][3], q2.x, wb0); ffma2(acc[ry][3], q2.y, wb1);
                }
            }
        }

        // Store chunk results (aligned float4)
        const int ox0 = tileX0 + lx;
        const int oy0 = yBase + c * CHUNK_H + ly;
#pragma unroll
        for (int ry = 0; ry < TY; ++ry) {
            float4 v;
            float lo, hi;
            unpack2(acc[ry][0], lo, hi); v.x = lo + hi;
            unpack2(acc[ry][1], lo, hi); v.y = lo + hi;
            unpack2(acc[ry][2], lo, hi); v.z = lo + hi;
            unpack2(acc[ry][3], lo, hi); v.w = lo + hi;
            *reinterpret_cast<float4*>(&outb[(size_t)(oy0 + ry) * IMG + ox0]) = v;
        }

        __syncthreads();
    }
#undef ISSUE_CHUNK
}

extern "C" void kernel_launch(void* const* d_in, const int* in_sizes, int n_in,
                              void* d_out, int out_size) {
    const float* X = (const float*)d_in[0];
    const float* W = (const float*)d_in[1];
    float* out = (float*)d_out;

    // Allow the large dynamic smem and request max smem carveout so 4 blocks
    // (4 x 41.3KB = 165.4KB) fit per SM. Attribute sets are host-side, no
    // allocation, idempotent -> graph-capture legal.
    cudaFuncSetAttribute(conv7x7_kernel,
                         cudaFuncAttributeMaxDynamicSharedMemorySize,
                         SMEM_BYTES);
    cudaFuncSetAttribute(conv7x7_kernel,
                         cudaFuncAttributePreferredSharedMemoryCarveout,
                         cudaSharedmemCarveoutMaxShared);

    // Build phase-pair table in device scratch, then stage into the constant
    // bank (device-to-device, graph-capturable).
    prep_weights<<<1, 64>>>(W);
    void* dst = nullptr;
    void* src = nullptr;
    cudaGetSymbolAddress(&dst, cWp);
    cudaGetSymbolAddress(&src, g_wp);
    cudaMemcpyAsync(dst, src, sizeof(g_wp), cudaMemcpyDeviceToDevice);

    dim3 block(BX, BY);
    dim3 grid(IMG / TILE_W, YGROUPS, 64);
    conv7x7_kernel<<<grid, block, SMEM_BYTES>>>(X, out);
}

// round 11
// speedup vs baseline: 1.0414x; 1.0382x over previous
#include <cuda_runtime.h>

// Conv2D 7x7, stride 1, pad 3. X [64,1024,1024] fp32 -> out [64,1024,1024].
// R11: validated R7 compute core (ir-outer single-load-per-row + FFMA2 phase
// trick + constant-bank weights). Structural changes:
//  - ONE __syncthreads per chunk (issue next chunk's cp.async AFTER the
//    barrier, so the trailing WAR-protection barrier is unnecessary)
//  - YGROUPS=4 (2048 blocks of 8 chunks) to shrink wave-quantization tail.

#define IMG 1024
#define KS 7
#define PAD 3

#define BX 32
#define BY 8
#define TX 4
#define TY 4
#define TILE_W (BX * TX)           // 128
#define CHUNK_H (BY * TY)          // 32 output rows per chunk
#define YGROUPS 4
#define YSPAN (IMG / YGROUPS)      // 256
#define NCHUNK (YSPAN / CHUNK_H)   // 8

#define IN_H (CHUNK_H + KS - 1)    // 38 input rows per chunk
#define PITCH 136                  // floats per smem row (544B, 16B-aligned)

typedef unsigned long long ull;

// Phase-pair weight tables.
// phase0: {w0,w1},{w2,w3},{w4,w5},{w6,0}
// phase1: {0,w0},{w1,w2},{w3,w4},{w5,w6}
__constant__ float2 cWp[KS][2][4];
__device__ float2 g_wp[KS][2][4];

__global__ void prep_weights(const float* __restrict__ W) {
    int t = threadIdx.x;
    if (t < KS * 8) {
        int ky = t >> 3;
        int r  = t & 7;
        int ph = r >> 2;
        int j  = r & 3;
        float lo, hi;
        if (ph == 0) {
            lo = W[ky * KS + 2 * j];
            hi = (2 * j + 1 < KS) ? W[ky * KS + 2 * j + 1] : 0.0f;
        } else {
            lo = (2 * j - 1 >= 0) ? W[ky * KS + 2 * j - 1] : 0.0f;
            hi = W[ky * KS + 2 * j];
        }
        g_wp[ky][ph][j] = make_float2(lo, hi);
    }
}

__device__ __forceinline__ void ffma2(ull& d, ull a, ull b) {
    asm("fma.rn.f32x2 %0, %1, %2, %0;" : "+l"(d) : "l"(a), "l"(b));
}
__device__ __forceinline__ ull pack2c(float2 v) {
    ull r;
    asm("mov.b64 %0, {%1, %2};" : "=l"(r) : "f"(v.x), "f"(v.y));
    return r;
}
__device__ __forceinline__ void unpack2(ull v, float& lo, float& hi) {
    asm("mov.b64 {%0, %1}, %2;" : "=f"(lo), "=f"(hi) : "l"(v));
}
__device__ __forceinline__ void cp_wait_all() {
    asm volatile("cp.async.wait_group 0;");
}
__device__ __forceinline__ void cp16(float* dst_smem, const float* src, bool ok) {
    unsigned saddr = (unsigned)__cvta_generic_to_shared(dst_smem);
    unsigned ss = ok ? 16u : 0u;
    asm volatile("cp.async.cg.shared.global [%0], [%1], 16, %2;"
                 :: "r"(saddr), "l"(src), "r"(ss));
}

__global__ __launch_bounds__(BX * BY, 4)
void conv7x7_kernel(const float* __restrict__ X,
                    float* __restrict__ out) {
    __shared__ __align__(16) float s_buf[2][IN_H * PITCH];

    const int tid = threadIdx.y * BX + threadIdx.x;

    const int tileX0 = blockIdx.x * TILE_W;
    const int yBase  = blockIdx.y * YSPAN;
    const int b      = blockIdx.z;
    const float* Xb  = X + (size_t)b * IMG * IMG;
    float* outb      = out + (size_t)b * IMG * IMG;

    const int gx0 = tileX0 - 4;           // 16B-aligned halo start

    // Per-thread cp.async addressing (hoisted; no division)
    const int c4m  = tid & 31;            // main col4 0..31
    const int r0m  = tid >> 5;            // row 0..7 (+8k)
    const int gxm  = gx0 + c4m * 4;
    const bool okxm = (gxm >= 0) && (gxm < IMG);
    const int rt_  = tid >> 1;            // tail row (tid < 76)
    const int c4t  = 32 + (tid & 1);
    const int gxt  = gx0 + c4t * 4;
    const bool okxt = (gxt < IMG);
    const bool tailact = (tid < 2 * IN_H);

    const int lx  = threadIdx.x * TX;     // local output col (multiple of 4)
    const int ly  = threadIdx.y * TY;     // local output row

#define ISSUE_CHUNK(SBUF, GY0)                                                  \
    do {                                                                        \
        const int gy0_ = (GY0);                                                 \
        _Pragma("unroll")                                                       \
        for (int k = 0; k < 5; ++k) {                                           \
            int r_ = r0m + k * 8;                                               \
            if (k < 4 || r_ < IN_H) {                                           \
                int gy_ = gy0_ + r_;                                            \
                bool ok_ = okxm && (gy_ >= 0) && (gy_ < IMG);                   \
                const float* src_ = ok_ ? (Xb + (size_t)gy_ * IMG + gxm) : Xb;  \
                cp16(&(SBUF)[r_ * PITCH + c4m * 4], src_, ok_);                 \
            }                                                                   \
        }                                                                       \
        if (tailact) {                                                          \
            int gy_ = gy0_ + rt_;                                               \
            bool ok_ = okxt && (gy_ >= 0) && (gy_ < IMG);                       \
            const float* src_ = ok_ ? (Xb + (size_t)gy_ * IMG + gxt) : Xb;      \
            cp16(&(SBUF)[rt_ * PITCH + c4t * 4], src_, ok_);                    \
        }                                                                       \
        asm volatile("cp.async.commit_group;");                                 \
    } while (0)

    // Prologue: load chunk 0
    ISSUE_CHUNK(s_buf[0], yBase - PAD);

    for (int c = 0; c < NCHUNK; ++c) {
        // Wait for chunk c (own group), then ONE barrier:
        //  - makes all warps' chunk-c copies visible to everyone
        //  - closes all reads of buf[(c+1)&1] from iteration c-1, so the
        //    cp.async issue below cannot clobber data still being read.
        cp_wait_all();
        __syncthreads();

        if (c + 1 < NCHUNK)
            ISSUE_CHUNK(s_buf[(c + 1) & 1], yBase + (c + 1) * CHUNK_H - PAD);

        const float* buf = s_buf[c & 1];

        ull acc[TY][TX];
#pragma unroll
        for (int ry = 0; ry < TY; ++ry)
#pragma unroll
            for (int ox = 0; ox < TX; ++ox) acc[ry][ox] = 0ull;

        // ir-outer: each input row loaded ONCE; feeds all valid
        // (ry, ky = ir - ry) cells. All guards are compile-time.
#pragma unroll
        for (int ir = 0; ir < TY + KS - 1; ++ir) {
            const ulonglong2* rowp = reinterpret_cast<const ulonglong2*>(
                &buf[(ly + ir) * PITCH + lx]);
            ulonglong2 q0 = rowp[0];   // p0, p1
            ulonglong2 q1 = rowp[1];   // p2, p3
            ulonglong2 q2 = rowp[2];   // p4, p5

#pragma unroll
            for (int ry = 0; ry < TY; ++ry) {
                const int ky = ir - ry;
                if (ky >= 0 && ky < KS) {
                    // 8 weight pairs for this ky from the constant bank
                    ull wa0 = pack2c(cWp[ky][0][0]);
                    ull wa1 = pack2c(cWp[ky][0][1]);
                    ull wb0 = pack2c(cWp[ky][0][2]);
                    ull wb1 = pack2c(cWp[ky][0][3]);
                    ull wc0 = pack2c(cWp[ky][1][0]);
                    ull wc1 = pack2c(cWp[ky][1][1]);
                    ull wd0 = pack2c(cWp[ky][1][2]);
                    ull wd1 = pack2c(cWp[ky][1][3]);

                    // ox=0: phase1 over p0..p3
                    ffma2(acc[ry][0], q0.x, wc0); ffma2(acc[ry][0], q0.y, wc1);
                    ffma2(acc[ry][0], q1.x, wd0); ffma2(acc[ry][0], q1.y, wd1);
                    // ox=1: phase0 over p1..p4
                    ffma2(acc[ry][1], q0.y, wa0); ffma2(acc[ry][1], q1.x, wa1);
                    ffma2(acc[ry][1], q1.y, wb0); ffma2(acc[ry][1], q2.x, wb1);
                    // ox=2: phase1 over p1..p4
                    ffma2(acc[ry][2], q0.y, wc0); ffma2(acc[ry][2], q1.x, wc1);
                    ffma2(acc[ry][2], q1.y, wd0); ffma2(acc[ry][2], q2.x, wd1);
                    // ox=3: phase0 over p2..p5
                    ffma2(acc[ry][3], q1.x, wa0); ffma2(acc[ry][3], q1.y, wa1);
                    ffma2(acc[ry][3], q2.x, wb0); ffma2(acc[ry][3], q2.y, wb1);
                }
            }
        }

        // Store chunk results (aligned float4)
        const int ox0 = tileX0 + lx;
        const int oy0 = yBase + c * CHUNK_H + ly;
#pragma unroll
        for (int ry = 0; ry < TY; ++ry) {
            float4 v;
            float lo, hi;
            unpack2(acc[ry][0], lo, hi); v.x = lo + hi;
            unpack2(acc[ry][1], lo, hi); v.y = lo + hi;
            unpack2(acc[ry][2], lo, hi); v.z = lo + hi;
            unpack2(acc[ry][3], lo, hi); v.w = lo + hi;
            *reinterpret_cast<float4*>(&outb[(size_t)(oy0 + ry) * IMG + ox0]) = v;
        }
        // NOTE: no trailing __syncthreads — WAR protection is provided by the
        // barrier at the top of the next iteration (cp.async issue moved
        // after it).
    }
#undef ISSUE_CHUNK
}

extern "C" void kernel_launch(void* const* d_in, const int* in_sizes, int n_in,
                              void* d_out, int out_size) {
    const float* X = (const float*)d_in[0];
    const float* W = (const float*)d_in[1];
    float* out = (float*)d_out;

    // Build phase-pair table in device scratch, then stage into the constant
    // bank (device-to-device, graph-capturable).
    prep_weights<<<1, 64>>>(W);
    void* dst = nullptr;
    void* src = nullptr;
    cudaGetSymbolAddress(&dst, cWp);
    cudaGetSymbolAddress(&src, g_wp);
    cudaMemcpyAsync(dst, src, sizeof(g_wp), cudaMemcpyDeviceToDevice);

    dim3 block(BX, BY);
    dim3 grid(IMG / TILE_W, YGROUPS, 64);
    conv7x7_kernel<<<grid, block>>>(X, out);
}